// round 15
// baseline (speedup 1.0000x reference)
#include <cuda_runtime.h>
#include <cuda_bf16.h>
#include <cstdint>

// out[b] = ||x_b||^2 * (x_b^T S x_b),  S=(rho+rho^T)/2, x=h+l, S=Sh+Sl:
//   q ~= h^T Sh (h + 2l) + h^T Sl h      (2-term; dropped O(eps^2))
// R15 = R13 (best total) + B-ldsm x4 merge (validated in R14) + early
// readiness signal (ticket taken before A-load so the grid-wide release
// waits only on conversion, not on each CTA's A-tile load).

#define BATCH 4096
#define DIMX 256
#define TILE_M 32
#define NTHREADS 512
#define NKCHUNKS 4            // K chunks of 64 cols
#define CHUNK_BYTES 32768     // 256 rows x 128 bytes

// chunk-major, swizzled: byte(r,c) = (c>>6)*32768 + r*128 + ((2*(c&63)) ^ ((r&7)<<4))
__device__ __nv_bfloat16 g_Sh[DIMX * DIMX];
__device__ __nv_bfloat16 g_Sl[DIMX * DIMX];
__device__ unsigned int g_cnt;   // monotonic ticket counter (replay-safe)

// ---- dynamic smem (bytes) ----
#define A_STRIDE 264          // bf16/row (528B pitch; ldsm conflict-free)
#define SM_AH    0                      // 32 x 528 = 16896
#define SM_AL    16896                  // -> 33792
#define SM_BH0   33792                  // 32768 -> 66560
#define SM_BL0   66560                  // -> 99328
#define SM_BH1   99328                  // -> 132096
#define SM_BL1   132096                 // -> 164864
#define SM_QP    164864                 // float[16][32] = 2048
#define SM_NP    166912                 // float[16][32] = 2048
#define SM_MB    168960                 // 2 x 8B mbarriers
#define SMEM_TOTAL 169088

__device__ __forceinline__ uint32_t smem_u32(const void* p) {
    uint32_t a;
    asm("{ .reg .u64 t; cvta.to.shared.u64 t, %1; cvt.u32.u64 %0, t; }"
        : "=r"(a) : "l"(p));
    return a;
}
__device__ __forceinline__ void mbar_init(uint32_t addr, uint32_t cnt) {
    asm volatile("mbarrier.init.shared.b64 [%0], %1;" :: "r"(addr), "r"(cnt) : "memory");
}
__device__ __forceinline__ void mbar_expect_tx(uint32_t addr, uint32_t bytes) {
    asm volatile("mbarrier.arrive.expect_tx.shared.b64 _, [%0], %1;"
                 :: "r"(addr), "r"(bytes) : "memory");
}
__device__ __forceinline__ void mbar_wait(uint32_t addr, uint32_t parity) {
    asm volatile(
        "{\n\t.reg .pred P;\n\t"
        "WL_%=:\n\t"
        "mbarrier.try_wait.parity.acquire.cta.shared::cta.b64 P, [%0], %1, 0x989680;\n\t"
        "@P bra.uni WD_%=;\n\t"
        "bra.uni WL_%=;\n\t"
        "WD_%=:\n\t}"
        :: "r"(addr), "r"(parity) : "memory");
}
__device__ __forceinline__ void bulk_g2s(uint32_t dst, const void* src,
                                         uint32_t bytes, uint32_t mbar) {
    asm volatile(
        "cp.async.bulk.shared::cta.global.mbarrier::complete_tx::bytes "
        "[%0], [%1], %2, [%3];"
        :: "r"(dst), "l"(src), "r"(bytes), "r"(mbar) : "memory");
}
__device__ __forceinline__ void mma16816(float* c, const uint32_t* a, const uint32_t* b) {
    asm volatile(
        "mma.sync.aligned.m16n8k16.row.col.f32.bf16.bf16.f32 "
        "{%0,%1,%2,%3}, {%4,%5,%6,%7}, {%8,%9}, {%0,%1,%2,%3};"
        : "+f"(c[0]), "+f"(c[1]), "+f"(c[2]), "+f"(c[3])
        : "r"(a[0]), "r"(a[1]), "r"(a[2]), "r"(a[3]), "r"(b[0]), "r"(b[1]));
}
__device__ __forceinline__ void ldsm_x4(uint32_t* r, uint32_t addr) {
    asm volatile("ldmatrix.sync.aligned.m8n8.x4.shared.b16 {%0,%1,%2,%3}, [%4];"
                 : "=r"(r[0]), "=r"(r[1]), "=r"(r[2]), "=r"(r[3]) : "r"(addr));
}
__device__ __forceinline__ void split4(const float4 v, uint2& hi, uint2& lo) {
    __nv_bfloat162 h01 = __float22bfloat162_rn(make_float2(v.x, v.y));
    __nv_bfloat162 h23 = __float22bfloat162_rn(make_float2(v.z, v.w));
    float2 f01 = __bfloat1622float2(h01);
    float2 f23 = __bfloat1622float2(h23);
    __nv_bfloat162 l01 = __float22bfloat162_rn(make_float2(v.x - f01.x, v.y - f01.y));
    __nv_bfloat162 l23 = __float22bfloat162_rn(make_float2(v.z - f23.x, v.w - f23.y));
    hi.x = *reinterpret_cast<const uint32_t*>(&h01);
    hi.y = *reinterpret_cast<const uint32_t*>(&h23);
    lo.x = *reinterpret_cast<const uint32_t*>(&l01);
    lo.y = *reinterpret_cast<const uint32_t*>(&l23);
}

__global__ __launch_bounds__(NTHREADS, 1)
void qmd_mma(const float* __restrict__ X, const float* __restrict__ R,
             float* __restrict__ out) {
    extern __shared__ char smem[];
    const uint32_t sb = smem_u32(smem);
    const int t = threadIdx.x;
    const int wid = t >> 5;
    const int lane = t & 31;
    const int b0 = blockIdx.x * TILE_M;

    if (t == 0) { mbar_init(sb + SM_MB, 1); mbar_init(sb + SM_MB + 8, 1); }

    // ---- phase 0: convert my 512 elements of S = (rho+rho^T)/2 ----
    {
        const int i = blockIdx.x * NTHREADS + t;    // 0..65535
        const int r = i >> 8, c = i & 255;
        const float s = 0.5f * (R[(size_t)r * DIMX + c] + R[(size_t)c * DIMX + r]);
        const __nv_bfloat16 h = __float2bfloat16(s);
        const __nv_bfloat16 l = __float2bfloat16(s - __bfloat162float(h));
        const uint32_t byte = (uint32_t)(c >> 6) * CHUNK_BYTES + r * 128
                              + (((c & 63) * 2) ^ ((r & 7) << 4));
        *reinterpret_cast<__nv_bfloat16*>(reinterpret_cast<char*>(g_Sh) + byte) = h;
        *reinterpret_cast<__nv_bfloat16*>(reinterpret_cast<char*>(g_Sl) + byte) = l;
    }
    __threadfence();                                  // S-writes globally visible
    __syncthreads();                                  // conversion done CTA-wide

    // ---- early readiness signal (ticket = signal; spin deferred) ----
    unsigned int target = 0;
    if (t == 0) {
        const unsigned int ticket = atomicAdd(&g_cnt, 1u);
        target = ((ticket >> 7) + 1u) << 7;           // next multiple of 128
    }

    // ---- phase 1: A tile load + split (off the cross-CTA critical path) ----
    {
        const float4* __restrict__ Xg = reinterpret_cast<const float4*>(X);
        #pragma unroll
        for (int i = 0; i < 4; i++) {
            const int f = t + i * NTHREADS;           // 0..2047
            const int r = f >> 6, c4 = f & 63;
            float4 v = Xg[(size_t)(b0 + r) * (DIMX / 4) + c4];
            uint2 hi, lo;
            split4(v, hi, lo);
            const uint32_t off = r * (A_STRIDE * 2) + c4 * 8;
            *reinterpret_cast<uint2*>(smem + SM_AH + off) = hi;
            *reinterpret_cast<uint2*>(smem + SM_AL + off) = lo;
        }
    }
    __syncthreads();                                  // A tile visible to all

    if (t == 0) {
        while (true) {                                // wait all 128 conversions
            unsigned int v;
            asm volatile("ld.global.acquire.gpu.u32 %0, [%1];"
                         : "=r"(v) : "l"(&g_cnt));
            if (v >= target) break;
        }
        const char* srch = reinterpret_cast<const char*>(g_Sh);
        const char* srcl = reinterpret_cast<const char*>(g_Sl);
        mbar_expect_tx(sb + SM_MB, 2 * CHUNK_BYTES);
        bulk_g2s(sb + SM_BH0, srch, CHUNK_BYTES, sb + SM_MB);
        bulk_g2s(sb + SM_BL0, srcl, CHUNK_BYTES, sb + SM_MB);
        mbar_expect_tx(sb + SM_MB + 8, 2 * CHUNK_BYTES);
        bulk_g2s(sb + SM_BH1, srch + CHUNK_BYTES, CHUNK_BYTES, sb + SM_MB + 8);
        bulk_g2s(sb + SM_BL1, srcl + CHUNK_BYTES, CHUNK_BYTES, sb + SM_MB + 8);
    }

    float acc_a[2][2][4], acc_b[2][2][4];
    #pragma unroll
    for (int mi = 0; mi < 2; mi++)
        #pragma unroll
        for (int ni = 0; ni < 2; ni++)
            #pragma unroll
            for (int e = 0; e < 4; e++) { acc_a[mi][ni][e] = 0.0f; acc_b[mi][ni][e] = 0.0f; }

    const int n_base = wid * 16;                      // warp's 16-col N slice
    // A ldsm addressing (padded pitch)
    const int m_idx = lane >> 3;
    const uint32_t a_rowoff = ((m_idx & 1) * 8 + (lane & 7)) * (A_STRIDE * 2)
                              + (m_idx >> 1) * 16;
    // B ldsm x4 addressing (swizzled 128B pitch):
    // grp0 = ni0@k0, grp1 = ni0@k8, grp2 = ni1@k0, grp3 = ni1@k8
    const uint32_t b_row = (uint32_t)(n_base + (m_idx >> 1) * 8 + (lane & 7)) * 128;
    const uint32_t b_sw  = (uint32_t)(lane & 7) << 4;
    const uint32_t b_kp  = (uint32_t)(m_idx & 1) * 16;

    for (int kb = 0; kb < NKCHUNKS; kb++) {
        const uint32_t st = kb & 1;
        mbar_wait(sb + SM_MB + 8 * st, (kb >> 1) & 1);

        const uint32_t bh = sb + (st ? SM_BH1 : SM_BH0);
        const uint32_t bl = sb + (st ? SM_BL1 : SM_BL0);

        #pragma unroll
        for (int k16 = 0; k16 < 4; k16++) {
            const int kcA = kb * 64 + k16 * 16;
            const uint32_t kcol = ((uint32_t)k16 * 32 + b_kp) ^ b_sw;

            uint32_t aH[2][4];
            #pragma unroll
            for (int mi = 0; mi < 2; mi++)
                ldsm_x4(aH[mi], sb + SM_AH + mi * 16 * (A_STRIDE * 2)
                                   + a_rowoff + kcA * 2);

            uint32_t bHf[4], bLf[4];
            ldsm_x4(bHf, bh + b_row + kcol);
            ldsm_x4(bLf, bl + b_row + kcol);

            #pragma unroll
            for (int mi = 0; mi < 2; mi++) {
                mma16816(acc_a[mi][0], aH[mi], &bHf[0]);   // h^T Sh, ni0
                mma16816(acc_a[mi][1], aH[mi], &bHf[2]);   // h^T Sh, ni1
                mma16816(acc_b[mi][0], aH[mi], &bLf[0]);   // h^T Sl, ni0
                mma16816(acc_b[mi][1], aH[mi], &bLf[2]);   // h^T Sl, ni1
            }
        }
        __syncthreads();                              // stage consumed by all

        if (kb < NKCHUNKS - 2 && t == 0) {            // re-arm + bulk chunk kb+2
            const int nk = kb + 2;
            const uint32_t mb = sb + SM_MB + 8 * st;
            const char* srch = reinterpret_cast<const char*>(g_Sh);
            const char* srcl = reinterpret_cast<const char*>(g_Sl);
            mbar_expect_tx(mb, 2 * CHUNK_BYTES);
            bulk_g2s(st ? sb + SM_BH1 : sb + SM_BH0,
                     srch + (size_t)nk * CHUNK_BYTES, CHUNK_BYTES, mb);
            bulk_g2s(st ? sb + SM_BL1 : sb + SM_BL0,
                     srcl + (size_t)nk * CHUNK_BYTES, CHUNK_BYTES, mb);
        }
    }

    // ---- fused epilogue: q = sum_j Za*(h+2l) + Zb*h ;  n = sum_j (h+l)^2 ----
    const __nv_bfloat16* sAh = reinterpret_cast<const __nv_bfloat16*>(smem + SM_AH);
    const __nv_bfloat16* sAl = reinterpret_cast<const __nv_bfloat16*>(smem + SM_AL);
    float q[4] = {0, 0, 0, 0};
    float nn[4] = {0, 0, 0, 0};
    #pragma unroll
    for (int mi = 0; mi < 2; mi++) {
        #pragma unroll
        for (int ni = 0; ni < 2; ni++) {
            const int j0 = n_base + ni * 8 + (lane & 3) * 2;
            const int r0 = mi * 16 + (lane >> 2);
            #pragma unroll
            for (int e = 0; e < 4; e++) {
                const int r = r0 + (e >> 1) * 8;
                const int j = j0 + (e & 1);
                const float xh = __bfloat162float(sAh[r * A_STRIDE + j]);
                const float xl = __bfloat162float(sAl[r * A_STRIDE + j]);
                const int slot = mi * 2 + (e >> 1);
                q[slot] = fmaf(acc_a[mi][ni][e], xh + 2.0f * xl, q[slot]);
                q[slot] = fmaf(acc_b[mi][ni][e], xh, q[slot]);
                const float xf = xh + xl;
                nn[slot] = fmaf(xf, xf, nn[slot]);
            }
        }
    }
    #pragma unroll
    for (int off = 1; off <= 2; off <<= 1) {
        #pragma unroll
        for (int s = 0; s < 4; s++) {
            q[s] += __shfl_xor_sync(0xffffffffu, q[s], off);
            nn[s] += __shfl_xor_sync(0xffffffffu, nn[s], off);
        }
    }
    float* qp = reinterpret_cast<float*>(smem + SM_QP);
    float* np = reinterpret_cast<float*>(smem + SM_NP);
    if ((lane & 3) == 0) {
        #pragma unroll
        for (int s = 0; s < 4; s++) {
            const int r = (lane >> 2) + s * 8;
            qp[wid * 32 + r] = q[s];
            np[wid * 32 + r] = nn[s];
        }
    }
    __syncthreads();

    if (t < TILE_M) {
        float qq = 0.0f, ns = 0.0f;
        #pragma unroll
        for (int w = 0; w < 16; w++) {
            qq += qp[w * 32 + t];
            ns += np[w * 32 + t];
        }
        out[b0 + t] = qq * ns;
    }
}

extern "C" void kernel_launch(void* const* d_in, const int* in_sizes, int n_in,
                              void* d_out, int out_size) {
    const float* X   = (const float*)d_in[0];
    const float* rho = (const float*)d_in[1];
    float* out = (float*)d_out;

    cudaFuncSetAttribute(qmd_mma, cudaFuncAttributeMaxDynamicSharedMemorySize, SMEM_TOTAL);
    qmd_mma<<<out_size / TILE_M, NTHREADS, SMEM_TOTAL>>>(X, rho, out);
}

// round 16
// speedup vs baseline: 1.0824x; 1.0824x over previous
#include <cuda_runtime.h>
#include <cuda_bf16.h>
#include <cstdint>

// out[b] = ||x_b||^2 * (x_b^T S x_b),  S=(rho+rho^T)/2, x=h+l, S=Sh+Sl:
//   q ~= h^T Sh (h + 2l) + h^T Sl h      (2-term; dropped O(eps^2))
// R16 = R13 handshake (proven) + x4 B-ldsm (proven) + TRIPLE-buffered B
// stages: chunks 0,1,2 prefetched up-front, only stage 0 recycled (chunk 3)
// -> exactly ONE mid-loop __syncthreads instead of three.

#define BATCH 4096
#define DIMX 256
#define TILE_M 32
#define NTHREADS 512
#define NKCHUNKS 4            // K chunks of 64 cols
#define CHUNK_BYTES 32768     // 256 rows x 128 bytes

// chunk-major, swizzled: byte(r,c) = (c>>6)*32768 + r*128 + ((2*(c&63)) ^ ((r&7)<<4))
__device__ __nv_bfloat16 g_Sh[DIMX * DIMX];
__device__ __nv_bfloat16 g_Sl[DIMX * DIMX];
__device__ unsigned int g_cnt;   // monotonic ticket counter (replay-safe)

// ---- dynamic smem (bytes) ----
#define A_STRIDE 264          // bf16/row (528B pitch; ldsm conflict-free)
#define SM_AH    0                      // 32 x 528 = 16896
#define SM_AL    16896                  // -> 33792
// stage s: Sh at SM_ST(s), Sl at SM_ST(s)+32768 ; stage size 65536
#define SM_ST0   33792                  // -> 99328
#define SM_ST1   99328                  // -> 164864
#define SM_ST2   164864                 // -> 230400
#define SM_MB    230400                 // 3 x 8B mbarriers
// QP/NP alias stage 1 (dead after mainloop + syncthreads)
#define SM_QP    99328                  // float[16][32] = 2048
#define SM_NP    101376                 // float[16][32] = 2048
#define SMEM_TOTAL 230464

__device__ __forceinline__ uint32_t smem_u32(const void* p) {
    uint32_t a;
    asm("{ .reg .u64 t; cvta.to.shared.u64 t, %1; cvt.u32.u64 %0, t; }"
        : "=r"(a) : "l"(p));
    return a;
}
__device__ __forceinline__ void mbar_init(uint32_t addr, uint32_t cnt) {
    asm volatile("mbarrier.init.shared.b64 [%0], %1;" :: "r"(addr), "r"(cnt) : "memory");
}
__device__ __forceinline__ void mbar_expect_tx(uint32_t addr, uint32_t bytes) {
    asm volatile("mbarrier.arrive.expect_tx.shared.b64 _, [%0], %1;"
                 :: "r"(addr), "r"(bytes) : "memory");
}
__device__ __forceinline__ void mbar_wait(uint32_t addr, uint32_t parity) {
    asm volatile(
        "{\n\t.reg .pred P;\n\t"
        "WL_%=:\n\t"
        "mbarrier.try_wait.parity.acquire.cta.shared::cta.b64 P, [%0], %1, 0x989680;\n\t"
        "@P bra.uni WD_%=;\n\t"
        "bra.uni WL_%=;\n\t"
        "WD_%=:\n\t}"
        :: "r"(addr), "r"(parity) : "memory");
}
__device__ __forceinline__ void bulk_g2s(uint32_t dst, const void* src,
                                         uint32_t bytes, uint32_t mbar) {
    asm volatile(
        "cp.async.bulk.shared::cta.global.mbarrier::complete_tx::bytes "
        "[%0], [%1], %2, [%3];"
        :: "r"(dst), "l"(src), "r"(bytes), "r"(mbar) : "memory");
}
__device__ __forceinline__ void mma16816(float* c, const uint32_t* a, const uint32_t* b) {
    asm volatile(
        "mma.sync.aligned.m16n8k16.row.col.f32.bf16.bf16.f32 "
        "{%0,%1,%2,%3}, {%4,%5,%6,%7}, {%8,%9}, {%0,%1,%2,%3};"
        : "+f"(c[0]), "+f"(c[1]), "+f"(c[2]), "+f"(c[3])
        : "r"(a[0]), "r"(a[1]), "r"(a[2]), "r"(a[3]), "r"(b[0]), "r"(b[1]));
}
__device__ __forceinline__ void ldsm_x4(uint32_t* r, uint32_t addr) {
    asm volatile("ldmatrix.sync.aligned.m8n8.x4.shared.b16 {%0,%1,%2,%3}, [%4];"
                 : "=r"(r[0]), "=r"(r[1]), "=r"(r[2]), "=r"(r[3]) : "r"(addr));
}
__device__ __forceinline__ void split4(const float4 v, uint2& hi, uint2& lo) {
    __nv_bfloat162 h01 = __float22bfloat162_rn(make_float2(v.x, v.y));
    __nv_bfloat162 h23 = __float22bfloat162_rn(make_float2(v.z, v.w));
    float2 f01 = __bfloat1622float2(h01);
    float2 f23 = __bfloat1622float2(h23);
    __nv_bfloat162 l01 = __float22bfloat162_rn(make_float2(v.x - f01.x, v.y - f01.y));
    __nv_bfloat162 l23 = __float22bfloat162_rn(make_float2(v.z - f23.x, v.w - f23.y));
    hi.x = *reinterpret_cast<const uint32_t*>(&h01);
    hi.y = *reinterpret_cast<const uint32_t*>(&h23);
    lo.x = *reinterpret_cast<const uint32_t*>(&l01);
    lo.y = *reinterpret_cast<const uint32_t*>(&l23);
}

__global__ __launch_bounds__(NTHREADS, 1)
void qmd_mma(const float* __restrict__ X, const float* __restrict__ R,
             float* __restrict__ out) {
    extern __shared__ char smem[];
    const uint32_t sb = smem_u32(smem);
    const int t = threadIdx.x;
    const int wid = t >> 5;
    const int lane = t & 31;
    const int b0 = blockIdx.x * TILE_M;

    if (t == 0) {
        mbar_init(sb + SM_MB, 1);
        mbar_init(sb + SM_MB + 8, 1);
        mbar_init(sb + SM_MB + 16, 1);
    }

    // ---- phase 0: convert my 512 elements of S = (rho+rho^T)/2 ----
    {
        const int i = blockIdx.x * NTHREADS + t;    // 0..65535
        const int r = i >> 8, c = i & 255;
        const float s = 0.5f * (R[(size_t)r * DIMX + c] + R[(size_t)c * DIMX + r]);
        const __nv_bfloat16 h = __float2bfloat16(s);
        const __nv_bfloat16 l = __float2bfloat16(s - __bfloat162float(h));
        const uint32_t byte = (uint32_t)(c >> 6) * CHUNK_BYTES + r * 128
                              + (((c & 63) * 2) ^ ((r & 7) << 4));
        *reinterpret_cast<__nv_bfloat16*>(reinterpret_cast<char*>(g_Sh) + byte) = h;
        *reinterpret_cast<__nv_bfloat16*>(reinterpret_cast<char*>(g_Sl) + byte) = l;
    }

    // ---- phase 1: A tile load + split ----
    {
        const float4* __restrict__ Xg = reinterpret_cast<const float4*>(X);
        #pragma unroll
        for (int i = 0; i < 4; i++) {
            const int f = t + i * NTHREADS;           // 0..2047
            const int r = f >> 6, c4 = f & 63;
            float4 v = Xg[(size_t)(b0 + r) * (DIMX / 4) + c4];
            uint2 hi, lo;
            split4(v, hi, lo);
            const uint32_t off = r * (A_STRIDE * 2) + c4 * 8;
            *reinterpret_cast<uint2*>(smem + SM_AH + off) = hi;
            *reinterpret_cast<uint2*>(smem + SM_AL + off) = lo;
        }
    }
    __threadfence();                                  // S-writes globally visible
    __syncthreads();

    // ---- grid-wide handshake (R13 placement) + prefetch chunks 0,1,2 ----
    if (t == 0) {
        const unsigned int ticket = atomicAdd(&g_cnt, 1u);
        const unsigned int target = ((ticket >> 7) + 1u) << 7;
        while (true) {
            unsigned int v;
            asm volatile("ld.global.acquire.gpu.u32 %0, [%1];"
                         : "=r"(v) : "l"(&g_cnt));
            if (v >= target) break;
        }
        const char* srch = reinterpret_cast<const char*>(g_Sh);
        const char* srcl = reinterpret_cast<const char*>(g_Sl);
        const uint32_t stb[3] = {sb + SM_ST0, sb + SM_ST1, sb + SM_ST2};
        #pragma unroll
        for (int s = 0; s < 3; s++) {
            mbar_expect_tx(sb + SM_MB + 8 * s, 2 * CHUNK_BYTES);
            bulk_g2s(stb[s],         srch + (size_t)s * CHUNK_BYTES, CHUNK_BYTES,
                     sb + SM_MB + 8 * s);
            bulk_g2s(stb[s] + CHUNK_BYTES, srcl + (size_t)s * CHUNK_BYTES, CHUNK_BYTES,
                     sb + SM_MB + 8 * s);
        }
    }

    float acc_a[2][2][4], acc_b[2][2][4];
    #pragma unroll
    for (int mi = 0; mi < 2; mi++)
        #pragma unroll
        for (int ni = 0; ni < 2; ni++)
            #pragma unroll
            for (int e = 0; e < 4; e++) { acc_a[mi][ni][e] = 0.0f; acc_b[mi][ni][e] = 0.0f; }

    const int n_base = wid * 16;                      // warp's 16-col N slice
    const int m_idx = lane >> 3;
    const uint32_t a_rowoff = ((m_idx & 1) * 8 + (lane & 7)) * (A_STRIDE * 2)
                              + (m_idx >> 1) * 16;
    // B ldsm x4: grp0 = ni0@k0, grp1 = ni0@k8, grp2 = ni1@k0, grp3 = ni1@k8
    const uint32_t b_row = (uint32_t)(n_base + (m_idx >> 1) * 8 + (lane & 7)) * 128;
    const uint32_t b_sw  = (uint32_t)(lane & 7) << 4;
    const uint32_t b_kp  = (uint32_t)(m_idx & 1) * 16;

    const uint32_t st_base[3] = {sb + SM_ST0, sb + SM_ST1, sb + SM_ST2};

    for (int kb = 0; kb < NKCHUNKS; kb++) {
        const int st = (kb == 3) ? 0 : kb;
        const uint32_t parity = (kb == 3) ? 1u : 0u;
        mbar_wait(sb + SM_MB + 8 * st, parity);

        const uint32_t bh = st_base[st];
        const uint32_t bl = st_base[st] + CHUNK_BYTES;

        #pragma unroll
        for (int k16 = 0; k16 < 4; k16++) {
            const int kcA = kb * 64 + k16 * 16;
            const uint32_t kcol = ((uint32_t)k16 * 32 + b_kp) ^ b_sw;

            uint32_t aH[2][4];
            #pragma unroll
            for (int mi = 0; mi < 2; mi++)
                ldsm_x4(aH[mi], sb + SM_AH + mi * 16 * (A_STRIDE * 2)
                                   + a_rowoff + kcA * 2);

            uint32_t bHf[4], bLf[4];
            ldsm_x4(bHf, bh + b_row + kcol);
            ldsm_x4(bLf, bl + b_row + kcol);

            #pragma unroll
            for (int mi = 0; mi < 2; mi++) {
                mma16816(acc_a[mi][0], aH[mi], &bHf[0]);   // h^T Sh, ni0
                mma16816(acc_a[mi][1], aH[mi], &bHf[2]);   // h^T Sh, ni1
                mma16816(acc_b[mi][0], aH[mi], &bLf[0]);   // h^T Sl, ni0
                mma16816(acc_b[mi][1], aH[mi], &bLf[2]);   // h^T Sl, ni1
            }
        }

        if (kb == 0) {                                // ONLY stage recycle point
            __syncthreads();                          // all warps done with st0
            if (t == 0) {
                const char* srch = reinterpret_cast<const char*>(g_Sh);
                const char* srcl = reinterpret_cast<const char*>(g_Sl);
                mbar_expect_tx(sb + SM_MB, 2 * CHUNK_BYTES);
                bulk_g2s(sb + SM_ST0, srch + (size_t)3 * CHUNK_BYTES,
                         CHUNK_BYTES, sb + SM_MB);
                bulk_g2s(sb + SM_ST0 + CHUNK_BYTES, srcl + (size_t)3 * CHUNK_BYTES,
                         CHUNK_BYTES, sb + SM_MB);
            }
        }
    }

    // ---- fused epilogue: q = sum_j Za*(h+2l) + Zb*h ;  n = sum_j (h+l)^2 ----
    const __nv_bfloat16* sAh = reinterpret_cast<const __nv_bfloat16*>(smem + SM_AH);
    const __nv_bfloat16* sAl = reinterpret_cast<const __nv_bfloat16*>(smem + SM_AL);
    float q[4] = {0, 0, 0, 0};
    float nn[4] = {0, 0, 0, 0};
    #pragma unroll
    for (int mi = 0; mi < 2; mi++) {
        #pragma unroll
        for (int ni = 0; ni < 2; ni++) {
            const int j0 = n_base + ni * 8 + (lane & 3) * 2;
            const int r0 = mi * 16 + (lane >> 2);
            #pragma unroll
            for (int e = 0; e < 4; e++) {
                const int r = r0 + (e >> 1) * 8;
                const int j = j0 + (e & 1);
                const float xh = __bfloat162float(sAh[r * A_STRIDE + j]);
                const float xl = __bfloat162float(sAl[r * A_STRIDE + j]);
                const int slot = mi * 2 + (e >> 1);
                q[slot] = fmaf(acc_a[mi][ni][e], xh + 2.0f * xl, q[slot]);
                q[slot] = fmaf(acc_b[mi][ni][e], xh, q[slot]);
                const float xf = xh + xl;
                nn[slot] = fmaf(xf, xf, nn[slot]);
            }
        }
    }
    #pragma unroll
    for (int off = 1; off <= 2; off <<= 1) {
        #pragma unroll
        for (int s = 0; s < 4; s++) {
            q[s] += __shfl_xor_sync(0xffffffffu, q[s], off);
            nn[s] += __shfl_xor_sync(0xffffffffu, nn[s], off);
        }
    }
    __syncthreads();                    // stage 1 fully dead -> alias QP/NP
    float* qp = reinterpret_cast<float*>(smem + SM_QP);
    float* np = reinterpret_cast<float*>(smem + SM_NP);
    if ((lane & 3) == 0) {
        #pragma unroll
        for (int s = 0; s < 4; s++) {
            const int r = (lane >> 2) + s * 8;
            qp[wid * 32 + r] = q[s];
            np[wid * 32 + r] = nn[s];
        }
    }
    __syncthreads();

    if (t < TILE_M) {
        float qq = 0.0f, ns = 0.0f;
        #pragma unroll
        for (int w = 0; w < 16; w++) {
            qq += qp[w * 32 + t];
            ns += np[w * 32 + t];
        }
        out[b0 + t] = qq * ns;
    }
}

extern "C" void kernel_launch(void* const* d_in, const int* in_sizes, int n_in,
                              void* d_out, int out_size) {
    const float* X   = (const float*)d_in[0];
    const float* rho = (const float*)d_in[1];
    float* out = (float*)d_out;

    cudaFuncSetAttribute(qmd_mma, cudaFuncAttributeMaxDynamicSharedMemorySize, SMEM_TOTAL);
    qmd_mma<<<out_size / TILE_M, NTHREADS, SMEM_TOTAL>>>(X, rho, out);
}

// round 17
// speedup vs baseline: 1.2186x; 1.1257x over previous
#include <cuda_runtime.h>
#include <cuda_bf16.h>
#include <cstdint>

// out[b] = ||x_b||^2 * (x_b^T S x_b),  S=(rho+rho^T)/2, x=h+l, S=Sh+Sl:
//   q ~= h^T Sh (h + 2l) + h^T Sl h      (2-term; dropped O(eps^2))
// R17: B never touches smem. Phase 0 packs S into mma-B-fragment order in
// gmem (L2-resident); the mainloop reads each B fragment with ONE coalesced
// LDG.128.cg per ni, triple-buffered in registers. No bulk copies, no
// mbarriers, no mid-loop barriers at all.

#define BATCH 4096
#define DIMX 256
#define TILE_M 32
#define NTHREADS 512

// fragment-major packed S: for (K16, n, i=lane%4) a 16B record
//   {hi:B[2i],B[2i+1], hi:B[2i+8],B[2i+9], lo: same}   (k relative to K16*16)
// byte(K16,n,i) = ((K16*256 + n)*4 + i)*16 ; total 16*256*4*16 = 256KB
__device__ __align__(16) unsigned char g_P[262144];
__device__ unsigned int g_cnt;   // monotonic ticket counter (replay-safe)

// ---- dynamic smem (bytes) ----
#define A_STRIDE 264          // bf16/row (528B pitch; ldsm conflict-free)
#define SM_AH    0                      // 32 x 528 = 16896
#define SM_AL    16896                  // -> 33792
#define SM_QP    33792                  // float[16][32] = 2048
#define SM_NP    35840                  // float[16][32] = 2048
#define SMEM_TOTAL 37888

__device__ __forceinline__ uint32_t smem_u32(const void* p) {
    uint32_t a;
    asm("{ .reg .u64 t; cvta.to.shared.u64 t, %1; cvt.u32.u64 %0, t; }"
        : "=r"(a) : "l"(p));
    return a;
}
__device__ __forceinline__ void ldg128_cg(uint4& v, const void* p) {
    asm volatile("ld.global.cg.v4.u32 {%0,%1,%2,%3}, [%4];"
                 : "=r"(v.x), "=r"(v.y), "=r"(v.z), "=r"(v.w) : "l"(p));
}
__device__ __forceinline__ void mma16816(float* c, const uint32_t* a, const uint32_t* b) {
    asm volatile(
        "mma.sync.aligned.m16n8k16.row.col.f32.bf16.bf16.f32 "
        "{%0,%1,%2,%3}, {%4,%5,%6,%7}, {%8,%9}, {%0,%1,%2,%3};"
        : "+f"(c[0]), "+f"(c[1]), "+f"(c[2]), "+f"(c[3])
        : "r"(a[0]), "r"(a[1]), "r"(a[2]), "r"(a[3]), "r"(b[0]), "r"(b[1]));
}
__device__ __forceinline__ void ldsm_x4(uint32_t* r, uint32_t addr) {
    asm volatile("ldmatrix.sync.aligned.m8n8.x4.shared.b16 {%0,%1,%2,%3}, [%4];"
                 : "=r"(r[0]), "=r"(r[1]), "=r"(r[2]), "=r"(r[3]) : "r"(addr));
}
__device__ __forceinline__ void split4(const float4 v, uint2& hi, uint2& lo) {
    __nv_bfloat162 h01 = __float22bfloat162_rn(make_float2(v.x, v.y));
    __nv_bfloat162 h23 = __float22bfloat162_rn(make_float2(v.z, v.w));
    float2 f01 = __bfloat1622float2(h01);
    float2 f23 = __bfloat1622float2(h23);
    __nv_bfloat162 l01 = __float22bfloat162_rn(make_float2(v.x - f01.x, v.y - f01.y));
    __nv_bfloat162 l23 = __float22bfloat162_rn(make_float2(v.z - f23.x, v.w - f23.y));
    hi.x = *reinterpret_cast<const uint32_t*>(&h01);
    hi.y = *reinterpret_cast<const uint32_t*>(&h23);
    lo.x = *reinterpret_cast<const uint32_t*>(&l01);
    lo.y = *reinterpret_cast<const uint32_t*>(&l23);
}

__global__ __launch_bounds__(NTHREADS, 1)
void qmd_mma(const float* __restrict__ X, const float* __restrict__ R,
             float* __restrict__ out) {
    extern __shared__ char smem[];
    const uint32_t sb = smem_u32(smem);
    const int t = threadIdx.x;
    const int wid = t >> 5;
    const int lane = t & 31;
    const int b0 = blockIdx.x * TILE_M;

    // ---- phase 0: convert my 512 elements of S into fragment-major g_P ----
    {
        const int i = blockIdx.x * NTHREADS + t;    // 0..65535
        const int r = i >> 8, c = i & 255;          // n = r, k = c
        const float s = 0.5f * (R[(size_t)r * DIMX + c] + R[(size_t)c * DIMX + r]);
        const __nv_bfloat16 h = __float2bfloat16(s);
        const __nv_bfloat16 l = __float2bfloat16(s - __bfloat162float(h));
        const int K16 = c >> 4, kr = c & 15;
        const int i4 = (kr >> 1) & 3;
        const int slot = (kr & 1) + ((kr >> 3) << 1);
        const uint32_t base = (uint32_t)(((K16 * 256 + r) * 4 + i4) * 16);
        *reinterpret_cast<__nv_bfloat16*>(g_P + base + slot * 2) = h;       // hi
        *reinterpret_cast<__nv_bfloat16*>(g_P + base + 8 + slot * 2) = l;   // lo
    }

    // ---- phase 1: A tile load + split ----
    {
        const float4* __restrict__ Xg = reinterpret_cast<const float4*>(X);
        #pragma unroll
        for (int i = 0; i < 4; i++) {
            const int f = t + i * NTHREADS;           // 0..2047
            const int r = f >> 6, c4 = f & 63;
            float4 v = Xg[(size_t)(b0 + r) * (DIMX / 4) + c4];
            uint2 hi, lo;
            split4(v, hi, lo);
            const uint32_t off = r * (A_STRIDE * 2) + c4 * 8;
            *reinterpret_cast<uint2*>(smem + SM_AH + off) = hi;
            *reinterpret_cast<uint2*>(smem + SM_AL + off) = lo;
        }
    }
    __threadfence();                                  // P-writes globally visible
    __syncthreads();

    // ---- grid-wide handshake (R13 placement), then release all warps ----
    if (t == 0) {
        const unsigned int ticket = atomicAdd(&g_cnt, 1u);
        const unsigned int target = ((ticket >> 7) + 1u) << 7;
        while (true) {
            unsigned int v;
            asm volatile("ld.global.acquire.gpu.u32 %0, [%1];"
                         : "=r"(v) : "l"(&g_cnt));
            if (v >= target) break;
        }
    }
    __syncthreads();                                  // all of S is packed

    float acc_a[2][2][4], acc_b[2][2][4];
    #pragma unroll
    for (int mi = 0; mi < 2; mi++)
        #pragma unroll
        for (int ni = 0; ni < 2; ni++)
            #pragma unroll
            for (int e = 0; e < 4; e++) { acc_a[mi][ni][e] = 0.0f; acc_b[mi][ni][e] = 0.0f; }

    const int n_base = wid * 16;                      // warp's 16-col N slice
    const int m_idx = lane >> 3;
    const uint32_t a_rowoff = ((m_idx & 1) * 8 + (lane & 7)) * (A_STRIDE * 2)
                              + (m_idx >> 1) * 16;
    // per-thread B fragment pointer: ni adds 512B, K16 adds 16384B
    const unsigned char* pB = g_P
        + ((uint32_t)(n_base + (lane >> 2)) * 4 + (lane & 3)) * 16;

    // ---- register triple-buffered B prefetch; barrier-free mainloop ----
    uint4 bf[3][2];
    #pragma unroll
    for (int s = 0; s < 3; s++) {
        ldg128_cg(bf[s][0], pB + s * 16384);
        ldg128_cg(bf[s][1], pB + s * 16384 + 512);
    }

    #pragma unroll
    for (int k16 = 0; k16 < 16; k16++) {
        const int cur = k16 % 3;

        uint32_t aH[2][4];
        #pragma unroll
        for (int mi = 0; mi < 2; mi++)
            ldsm_x4(aH[mi], sb + SM_AH + mi * 16 * (A_STRIDE * 2)
                               + a_rowoff + (k16 * 16) * 2);

        #pragma unroll
        for (int mi = 0; mi < 2; mi++) {
            #pragma unroll
            for (int ni = 0; ni < 2; ni++) {
                const uint32_t* bp = reinterpret_cast<const uint32_t*>(&bf[cur][ni]);
                mma16816(acc_a[mi][ni], aH[mi], bp);       // h^T Sh (hi regs)
                mma16816(acc_b[mi][ni], aH[mi], bp + 2);   // h^T Sl (lo regs)
            }
        }

        if (k16 < 13) {                               // refill slot for k16+3
            ldg128_cg(bf[cur][0], pB + (k16 + 3) * 16384);
            ldg128_cg(bf[cur][1], pB + (k16 + 3) * 16384 + 512);
        }
    }

    // ---- fused epilogue: q = sum_j Za*(h+2l) + Zb*h ;  n = sum_j (h+l)^2 ----
    const __nv_bfloat16* sAh = reinterpret_cast<const __nv_bfloat16*>(smem + SM_AH);
    const __nv_bfloat16* sAl = reinterpret_cast<const __nv_bfloat16*>(smem + SM_AL);
    float q[4] = {0, 0, 0, 0};
    float nn[4] = {0, 0, 0, 0};
    #pragma unroll
    for (int mi = 0; mi < 2; mi++) {
        #pragma unroll
        for (int ni = 0; ni < 2; ni++) {
            const int j0 = n_base + ni * 8 + (lane & 3) * 2;
            const int r0 = mi * 16 + (lane >> 2);
            #pragma unroll
            for (int e = 0; e < 4; e++) {
                const int r = r0 + (e >> 1) * 8;
                const int j = j0 + (e & 1);
                const float xh = __bfloat162float(sAh[r * A_STRIDE + j]);
                const float xl = __bfloat162float(sAl[r * A_STRIDE + j]);
                const int slot = mi * 2 + (e >> 1);
                q[slot] = fmaf(acc_a[mi][ni][e], xh + 2.0f * xl, q[slot]);
                q[slot] = fmaf(acc_b[mi][ni][e], xh, q[slot]);
                const float xf = xh + xl;
                nn[slot] = fmaf(xf, xf, nn[slot]);
            }
        }
    }
    #pragma unroll
    for (int off = 1; off <= 2; off <<= 1) {
        #pragma unroll
        for (int s = 0; s < 4; s++) {
            q[s] += __shfl_xor_sync(0xffffffffu, q[s], off);
            nn[s] += __shfl_xor_sync(0xffffffffu, nn[s], off);
        }
    }
    float* qp = reinterpret_cast<float*>(smem + SM_QP);
    float* np = reinterpret_cast<float*>(smem + SM_NP);
    if ((lane & 3) == 0) {
        #pragma unroll
        for (int s = 0; s < 4; s++) {
            const int r = (lane >> 2) + s * 8;
            qp[wid * 32 + r] = q[s];
            np[wid * 32 + r] = nn[s];
        }
    }
    __syncthreads();

    if (t < TILE_M) {
        float qq = 0.0f, ns = 0.0f;
        #pragma unroll
        for (int w = 0; w < 16; w++) {
            qq += qp[w * 32 + t];
            ns += np[w * 32 + t];
        }
        out[b0 + t] = qq * ns;
    }
}

extern "C" void kernel_launch(void* const* d_in, const int* in_sizes, int n_in,
                              void* d_out, int out_size) {
    const float* X   = (const float*)d_in[0];
    const float* rho = (const float*)d_in[1];
    float* out = (float*)d_out;

    cudaFuncSetAttribute(qmd_mma, cudaFuncAttributeMaxDynamicSharedMemorySize, SMEM_TOTAL);
    qmd_mma<<<out_size / TILE_M, NTHREADS, SMEM_TOTAL>>>(X, rho, out);
}